// round 11
// baseline (speedup 1.0000x reference)
#include <cuda_runtime.h>
#include <math.h>
#include <stdint.h>

// ---------------------------------------------------------------------------
// Problem constants
// ---------------------------------------------------------------------------
constexpr int E     = 256;
constexpr int BATCH = 512;
constexpr int NNEG  = 2048;
constexpr int K2    = 512;           // expanded GEMM K

// Fragment-packed scratch:
//  g_A: [mAtom=32][kAtom=64][lane=32][reg=4]   (A' = [b^2 | -2ab], tf32)
//  g_T: [nAtom=256][kPair=32][lane=32][f=4]    (T' = [t^2 | t],   tf32)
//       f = (kAtom&1)*2 + reg  (kPair = kAtom>>1)
__device__ float g_A[BATCH * K2];
__device__ float g_T[NNEG  * K2];
__device__ float g_alpha[BATCH];     // sum a^2

__device__ __forceinline__ float to_tf32(float x) {
    uint32_t u;
    asm("cvt.rna.tf32.f32 %0, %1;" : "=r"(u) : "f"(x));
    return __uint_as_float(u);
}
__device__ __forceinline__ uint32_t smem_u32(const void* p) {
    uint32_t a;
    asm("{ .reg .u64 t; cvta.to.shared.u64 t, %1; cvt.u32.u64 %0, t; }" : "=r"(a) : "l"(p));
    return a;
}

#define CP_ASYNC16(sm, gp) \
    asm volatile("cp.async.cg.shared.global [%0], [%1], 16;" :: "r"(sm), "l"(gp) : "memory")
#define CP_COMMIT() asm volatile("cp.async.commit_group;" ::: "memory")
#define CP_WAIT(n)  asm volatile("cp.async.wait_group %0;" :: "n"(n) : "memory")

// ---------------------------------------------------------------------------
// Prep: blocks 0..31 head mAtoms (16 rows), blocks 32..287 tail nAtoms (8 rows).
// Stage normalized rows in smem, then emit fragment-packed blocks with
// STG.128 and fully coalesced addresses.
// ---------------------------------------------------------------------------
constexpr int PITCH = 260;   // bank = (4*row + col)&31 -> conflict-free packed reads

__global__ __launch_bounds__(256) void prep_kernel(const float* __restrict__ head,
                                                   const float* __restrict__ tail,
                                                   const float* __restrict__ rel,
                                                   const int*   __restrict__ rid) {
    __shared__ float sa[16 * PITCH];   // head: a rows | tail: t rows (8 used)
    __shared__ float sbv[16 * PITCH];  // head: b rows

    const int tid = threadIdx.x;

    if (blockIdx.x < 32) {
        // ---------------- head mAtom block: rows m0*16 .. +15 ----------------
        const int m0 = blockIdx.x;
        const int ty = tid >> 4;      // row 0..15
        const int tx = tid & 15;
        const int i  = m0 * 16 + ty;

        float h[16];
        float ss = 0.0f;
        #pragma unroll
        for (int q = 0; q < 16; q++) {
            h[q] = head[i * E + q * 16 + tx];
            ss += h[q] * h[q];
        }
        #pragma unroll
        for (int o = 8; o > 0; o >>= 1) ss += __shfl_xor_sync(0xffffffffu, ss, o);
        float inv = 1.0f / fmaxf(sqrtf(ss), 1e-12f);

        const int r = rid[i];
        const float* rrow = &rel[(long)r * (2 * E)];
        float asq = 0.0f;
        #pragma unroll
        for (int q = 0; q < 16; q++) {
            int k = q * 16 + tx;
            float a = (h[q] * inv) * rrow[k];
            float b = rrow[E + k];
            sa [ty * PITCH + k] = a;
            sbv[ty * PITCH + k] = b;
            asq += a * a;
        }
        #pragma unroll
        for (int o = 8; o > 0; o >>= 1) asq += __shfl_xor_sync(0xffffffffu, asq, o);
        if (tx == 0) g_alpha[i] = asq;
        __syncthreads();

        // packed write: 2048 float4, 8 per thread, coalesced STG.128
        #pragma unroll
        for (int p = 0; p < 8; p++) {
            int q4    = tid + p * 256;       // 0..2047
            int kAtom = q4 >> 5;             // 0..63
            int lane  = q4 & 31;
            int rr    = lane >> 2;
            int klo   = (kAtom & 31) * 8 + (lane & 3);
            float4 v;
            if (kAtom < 32) {
                float b00 = sbv[rr * PITCH + klo];
                float b10 = sbv[(rr + 8) * PITCH + klo];
                float b01 = sbv[rr * PITCH + klo + 4];
                float b11 = sbv[(rr + 8) * PITCH + klo + 4];
                v = make_float4(to_tf32(b00 * b00), to_tf32(b10 * b10),
                                to_tf32(b01 * b01), to_tf32(b11 * b11));
            } else {
                float a00 = sa[rr * PITCH + klo],       b00 = sbv[rr * PITCH + klo];
                float a10 = sa[(rr + 8) * PITCH + klo], b10 = sbv[(rr + 8) * PITCH + klo];
                float a01 = sa[rr * PITCH + klo + 4],   b01 = sbv[rr * PITCH + klo + 4];
                float a11 = sa[(rr + 8) * PITCH + klo + 4], b11 = sbv[(rr + 8) * PITCH + klo + 4];
                v = make_float4(to_tf32(-2.0f * a00 * b00), to_tf32(-2.0f * a10 * b10),
                                to_tf32(-2.0f * a01 * b01), to_tf32(-2.0f * a11 * b11));
            }
            *reinterpret_cast<float4*>(&g_A[((m0 * 64 + kAtom) * 32 + lane) * 4]) = v;
        }
    } else {
        // ---------------- tail nAtom block: rows n0*8 .. +7 ----------------
        const int n0 = blockIdx.x - 32;
        const int ty = tid >> 5;      // row 0..7 (one warp per row)
        const int tx = tid & 31;
        const int j  = n0 * 8 + ty;

        float t[8];
        float ss = 0.0f;
        #pragma unroll
        for (int q = 0; q < 8; q++) {
            t[q] = tail[j * E + q * 32 + tx];
            ss += t[q] * t[q];
        }
        #pragma unroll
        for (int o = 16; o > 0; o >>= 1) ss += __shfl_xor_sync(0xffffffffu, ss, o);
        float inv = 1.0f / fmaxf(sqrtf(ss), 1e-12f);

        #pragma unroll
        for (int q = 0; q < 8; q++)
            sa[ty * PITCH + q * 32 + tx] = t[q] * inv;
        __syncthreads();

        // packed write: 1024 float4, 4 per thread, coalesced STG.128
        #pragma unroll
        for (int p = 0; p < 4; p++) {
            int q4    = tid + p * 256;       // 0..1023
            int kPair = q4 >> 5;             // 0..31
            int lane  = q4 & 31;
            int rr    = lane >> 2;
            int kA0   = 2 * kPair;
            int b0    = (kA0 & 31) * 8 + (lane & 3);
            int b1    = ((kA0 + 1) & 31) * 8 + (lane & 3);
            float t00 = sa[rr * PITCH + b0], t01 = sa[rr * PITCH + b0 + 4];
            float t10 = sa[rr * PITCH + b1], t11 = sa[rr * PITCH + b1 + 4];
            float4 v;
            if (kA0 < 32)
                v = make_float4(to_tf32(t00 * t00), to_tf32(t01 * t01),
                                to_tf32(t10 * t10), to_tf32(t11 * t11));
            else
                v = make_float4(to_tf32(t00), to_tf32(t01),
                                to_tf32(t10), to_tf32(t11));
            *reinterpret_cast<float4*>(&g_T[((n0 * 32 + kPair) * 32 + lane) * 4]) = v;
        }
    }
}

// ---------------------------------------------------------------------------
// Main: tf32 mma.sync GEMM on fragment-packed operands.
// CTA tile 64x128 (4 mAtoms x 16 nAtoms), 512 threads, 16 warps as 4x4,
// warp tile 16x32. K=512 in 8 chunks of 64 (BK=64). 3-stage cp.async pipeline.
// All fragment loads are contiguous-512B LDS.128 (conflict-free).
// ---------------------------------------------------------------------------
constexpr int NCHUNK   = 8;
constexpr int NSTAGE   = 3;
constexpr int A_WORDS  = 4 * 8 * 32 * 4;           // 4096  (4 mAtoms x 8 kAtoms)
constexpr int B_WORDS  = 16 * 4 * 32 * 4;          // 8192  (16 nAtoms x 4 kPairs)
constexpr int BUF_WORDS = A_WORDS + B_WORDS;       // 12288 (48 KB)
constexpr int SMEM_BYTES = NSTAGE * BUF_WORDS * 4; // 147456

__device__ __forceinline__ void mma_tf32(float d[4], const uint32_t a[4], uint32_t b0, uint32_t b1) {
    asm volatile(
        "mma.sync.aligned.m16n8k8.row.col.f32.tf32.tf32.f32 "
        "{%0,%1,%2,%3}, {%4,%5,%6,%7}, {%8,%9}, {%0,%1,%2,%3};"
        : "+f"(d[0]), "+f"(d[1]), "+f"(d[2]), "+f"(d[3])
        : "r"(a[0]), "r"(a[1]), "r"(a[2]), "r"(a[3]), "r"(b0), "r"(b1));
}

__global__ __launch_bounds__(512, 1) void pairre_mma_kernel(float* __restrict__ out) {
    extern __shared__ __align__(16) float smem[];
    const uint32_t sb = smem_u32(smem);

    const int tid  = threadIdx.x;
    const int wid  = tid >> 5;
    const int lane = tid & 31;
    const int ib  = blockIdx.y * 64;
    const int jb  = blockIdx.x * 128;
    const int ibA = blockIdx.y * 4;      // first mAtom
    const int jbA = blockIdx.x * 16;     // first nAtom

    const int wmA = wid >> 2;            // warp's mAtom (0..3)
    const int wnA = (wid & 3) * 4;       // warp's first nAtom (0..12)
    const int g   = lane >> 2;
    const int t   = lane & 3;

    float d[4][4];
    #pragma unroll
    for (int na = 0; na < 4; na++)
        #pragma unroll
        for (int q = 0; q < 4; q++)
            d[na][q] = 0.0f;

    auto issue_chunk = [&](int c, int stage) {
        const uint32_t bufA = sb + (stage * BUF_WORDS) * 4;
        const uint32_t bufB = bufA + A_WORDS * 4;
        // A: 1024 float4 (4 mAtom segments of 1024 floats) — 2 per thread
        #pragma unroll
        for (int p = 0; p < 2; p++) {
            int f4i = tid + p * 512;          // 0..1023
            int m   = f4i >> 8;
            int off = (f4i & 255) * 4;
            CP_ASYNC16(bufA + (m * 1024 + off) * 4,
                       &g_A[((ibA + m) * 64 + 8 * c) * 128 + off]);
        }
        // B: 2048 float4 (16 nAtom segments of 512 floats) — 4 per thread
        #pragma unroll
        for (int p = 0; p < 4; p++) {
            int f4i = tid + p * 512;          // 0..2047
            int nA  = f4i >> 7;
            int off = (f4i & 127) * 4;
            CP_ASYNC16(bufB + (nA * 512 + off) * 4,
                       &g_T[((jbA + nA) * 32 + 4 * c) * 128 + off]);
        }
        CP_COMMIT();
    };

    issue_chunk(0, 0);
    issue_chunk(1, 1);

    for (int c = 0; c < NCHUNK; c++) {
        if (c + 1 < NCHUNK) { CP_WAIT(1); } else { CP_WAIT(0); }
        __syncthreads();
        if (c + 2 < NCHUNK) issue_chunk(c + 2, (c + 2) % NSTAGE);

        const int stage = c % NSTAGE;
        const float* SA = smem + stage * BUF_WORDS;
        const float* SB = SA + A_WORDS;

        #pragma unroll
        for (int kp = 0; kp < 4; kp++) {
            // B: one LDS.128 per nAtom feeds two k-steps
            float4 b4[4];
            #pragma unroll
            for (int na = 0; na < 4; na++)
                b4[na] = *reinterpret_cast<const float4*>(
                    &SB[((wnA + na) * 4 + kp) * 128 + lane * 4]);
            // A: two LDS.128 (k-steps 2kp, 2kp+1)
            float4 a0 = *reinterpret_cast<const float4*>(
                &SA[(wmA * 8 + 2 * kp) * 128 + lane * 4]);
            float4 a1 = *reinterpret_cast<const float4*>(
                &SA[(wmA * 8 + 2 * kp + 1) * 128 + lane * 4]);
            uint32_t af0[4] = {__float_as_uint(a0.x), __float_as_uint(a0.y),
                               __float_as_uint(a0.z), __float_as_uint(a0.w)};
            uint32_t af1[4] = {__float_as_uint(a1.x), __float_as_uint(a1.y),
                               __float_as_uint(a1.z), __float_as_uint(a1.w)};
            #pragma unroll
            for (int na = 0; na < 4; na++)
                mma_tf32(d[na], af0, __float_as_uint(b4[na].x), __float_as_uint(b4[na].y));
            #pragma unroll
            for (int na = 0; na < 4; na++)
                mma_tf32(d[na], af1, __float_as_uint(b4[na].z), __float_as_uint(b4[na].w));
        }
    }

    // Epilogue: out[i,j] = -sqrt(max(d + alpha_i, 0))
    const int i0 = ib + wmA * 16 + g;
    const float al0 = g_alpha[i0];
    const float al1 = g_alpha[i0 + 8];
    #pragma unroll
    for (int na = 0; na < 4; na++) {
        const int j = jb + (wnA + na) * 8 + t * 2;
        float2 v0, v1;
        v0.x = -sqrtf(fmaxf(d[na][0] + al0, 0.0f));
        v0.y = -sqrtf(fmaxf(d[na][1] + al0, 0.0f));
        v1.x = -sqrtf(fmaxf(d[na][2] + al1, 0.0f));
        v1.y = -sqrtf(fmaxf(d[na][3] + al1, 0.0f));
        *reinterpret_cast<float2*>(&out[i0 * NNEG + j])       = v0;
        *reinterpret_cast<float2*>(&out[(i0 + 8) * NNEG + j]) = v1;
    }
}

// ---------------------------------------------------------------------------
// Launch
// ---------------------------------------------------------------------------
extern "C" void kernel_launch(void* const* d_in, const int* in_sizes, int n_in,
                              void* d_out, int out_size) {
    const float* head = (const float*)d_in[0];   // (512, 256)
    const float* tail = (const float*)d_in[1];   // (1, 2048, 256)
    const float* rel  = (const float*)d_in[2];   // (1000, 512)
    const int*   rid  = (const int*)d_in[3];     // (512,) int32 on the wire
    float* out = (float*)d_out;                  // (512, 2048)

    cudaFuncSetAttribute(pairre_mma_kernel,
                         cudaFuncAttributeMaxDynamicSharedMemorySize, SMEM_BYTES);

    prep_kernel<<<32 + NNEG / 8, 256>>>(head, tail, rel, rid);   // 288 blocks

    dim3 grid(NNEG / 128, BATCH / 64);   // (16, 8) = 128 CTAs
    pairre_mma_kernel<<<grid, 512, SMEM_BYTES>>>(out);
}

// round 15
// speedup vs baseline: 1.5661x; 1.5661x over previous
#include <cuda_runtime.h>
#include <cuda_fp16.h>
#include <math.h>
#include <stdint.h>

// ---------------------------------------------------------------------------
// Problem constants
// ---------------------------------------------------------------------------
constexpr int E     = 256;
constexpr int BATCH = 512;
constexpr int NNEG  = 2048;
constexpr int K2    = 512;           // expanded GEMM K

// Fragment-packed fp16 scratch (m16n8k16 fragments, one uint4 per lane/atom):
//  g_Apk: [mAtom=32][kAtom=32][lane=32][4xu32]   A' = [b^2 | -2ab]
//  g_Tpk: [nAtom=256][kPair=16][lane=32][4xu32]  T' = [t^2 | t]
__device__ __align__(16) uint32_t g_Apk[32 * 32 * 32 * 4];    // 512 KB
__device__ __align__(16) uint32_t g_Tpk[256 * 16 * 32 * 4];   // 2 MB
__device__ float g_alpha[BATCH];     // sum a^2 (fp32)

__device__ __forceinline__ uint32_t smem_u32(const void* p) {
    uint32_t a;
    asm("{ .reg .u64 t; cvta.to.shared.u64 t, %1; cvt.u32.u64 %0, t; }" : "=r"(a) : "l"(p));
    return a;
}
__device__ __forceinline__ uint32_t h2u(float lo, float hi) {
    __half2 h = __floats2half2_rn(lo, hi);
    return *reinterpret_cast<uint32_t*>(&h);
}

#define CP_ASYNC16(sm, gp) \
    asm volatile("cp.async.cg.shared.global [%0], [%1], 16;" :: "r"(sm), "l"(gp) : "memory")
#define CP_COMMIT() asm volatile("cp.async.commit_group;" ::: "memory")
#define CP_WAIT(n)  asm volatile("cp.async.wait_group %0;" :: "n"(n) : "memory")

// ---------------------------------------------------------------------------
// Prep: blocks 0..31 head mAtoms (16 rows), blocks 32..287 tail nAtoms (8 rows).
// Stage normalized rows in smem, emit fp16 fragment-packed uint4 blocks,
// fully coalesced STG.128.
// ---------------------------------------------------------------------------
constexpr int PITCH = 260;

__global__ __launch_bounds__(256) void prep_kernel(const float* __restrict__ head,
                                                   const float* __restrict__ tail,
                                                   const float* __restrict__ rel,
                                                   const int*   __restrict__ rid) {
    __shared__ float sa[16 * PITCH];   // head: a rows | tail: t rows (8 used)
    __shared__ float sbv[16 * PITCH];  // head: b rows

    const int tid = threadIdx.x;

    if (blockIdx.x < 32) {
        // ---------------- head mAtom block: rows m0*16 .. +15 ----------------
        const int m0 = blockIdx.x;
        const int ty = tid >> 4;      // row 0..15
        const int tx = tid & 15;
        const int i  = m0 * 16 + ty;

        float h[16];
        float ss = 0.0f;
        #pragma unroll
        for (int q = 0; q < 16; q++) {
            h[q] = head[i * E + q * 16 + tx];
            ss += h[q] * h[q];
        }
        #pragma unroll
        for (int o = 8; o > 0; o >>= 1) ss += __shfl_xor_sync(0xffffffffu, ss, o);
        float inv = 1.0f / fmaxf(sqrtf(ss), 1e-12f);

        const int r = rid[i];
        const float* rrow = &rel[(long)r * (2 * E)];
        float asq = 0.0f;
        #pragma unroll
        for (int q = 0; q < 16; q++) {
            int k = q * 16 + tx;
            float a = (h[q] * inv) * rrow[k];
            float b = rrow[E + k];
            sa [ty * PITCH + k] = a;
            sbv[ty * PITCH + k] = b;
            asq += a * a;
        }
        #pragma unroll
        for (int o = 8; o > 0; o >>= 1) asq += __shfl_xor_sync(0xffffffffu, asq, o);
        if (tx == 0) g_alpha[i] = asq;
        __syncthreads();

        // packed write: 32 kAtoms x 32 lanes = 1024 uint4, 4 per thread
        #pragma unroll
        for (int p = 0; p < 4; p++) {
            int q4    = tid + p * 256;        // 0..1023
            int kAtom = q4 >> 5;              // 0..31
            int lane  = q4 & 31;
            int rr    = lane >> 2;
            int c0    = (kAtom & 15) * 16 + (lane & 3) * 2;
            bool sq   = (kAtom < 16);         // b^2 half vs -2ab half

            auto val = [&](int row, int col) -> float {
                float b = sbv[row * PITCH + col];
                return sq ? b * b : -2.0f * sa[row * PITCH + col] * b;
            };
            uint4 v;
            v.x = h2u(val(rr, c0),         val(rr, c0 + 1));
            v.y = h2u(val(rr + 8, c0),     val(rr + 8, c0 + 1));
            v.z = h2u(val(rr, c0 + 8),     val(rr, c0 + 9));
            v.w = h2u(val(rr + 8, c0 + 8), val(rr + 8, c0 + 9));
            *reinterpret_cast<uint4*>(&g_Apk[((m0 * 32 + kAtom) * 32 + lane) * 4]) = v;
        }
    } else {
        // ---------------- tail nAtom block: rows n0*8 .. +7 ----------------
        const int n0 = blockIdx.x - 32;
        const int ty = tid >> 5;      // row 0..7 (one warp per row)
        const int tx = tid & 31;
        const int j  = n0 * 8 + ty;

        float t[8];
        float ss = 0.0f;
        #pragma unroll
        for (int q = 0; q < 8; q++) {
            t[q] = tail[j * E + q * 32 + tx];
            ss += t[q] * t[q];
        }
        #pragma unroll
        for (int o = 16; o > 0; o >>= 1) ss += __shfl_xor_sync(0xffffffffu, ss, o);
        float inv = 1.0f / fmaxf(sqrtf(ss), 1e-12f);

        #pragma unroll
        for (int q = 0; q < 8; q++)
            sa[ty * PITCH + q * 32 + tx] = t[q] * inv;
        __syncthreads();

        // packed write: 16 kPairs x 32 lanes = 512 uint4, 2 per thread
        #pragma unroll
        for (int p = 0; p < 2; p++) {
            int q4    = tid + p * 256;        // 0..511
            int kPair = q4 >> 5;              // 0..15
            int lane  = q4 & 31;
            int jl    = lane >> 2;            // n within atom
            int tg    = lane & 3;
            int kb    = kPair * 32;

            auto tval = [&](int klog) -> float {
                float tv = sa[jl * PITCH + (klog & 255)];
                return (klog < 256) ? tv * tv : tv;
            };
            uint4 v;
            v.x = h2u(tval(kb + 2 * tg),          tval(kb + 2 * tg + 1));
            v.y = h2u(tval(kb + 2 * tg + 8),      tval(kb + 2 * tg + 9));
            v.z = h2u(tval(kb + 16 + 2 * tg),     tval(kb + 16 + 2 * tg + 1));
            v.w = h2u(tval(kb + 16 + 2 * tg + 8), tval(kb + 16 + 2 * tg + 9));
            *reinterpret_cast<uint4*>(&g_Tpk[((n0 * 16 + kPair) * 32 + lane) * 4]) = v;
        }
    }
}

// ---------------------------------------------------------------------------
// Main: fp16 mma.sync m16n8k16 GEMM on fragment-packed operands.
// CTA tile 64x128 (4 mAtoms x 16 nAtoms), 512 threads, 16 warps (4x4),
// warp tile 16x32. K=512 in 8 chunks of 64 (4 kAtoms / 2 kPairs).
// 3-stage cp.async pipeline; all fragment loads contiguous LDS.128.
// ---------------------------------------------------------------------------
constexpr int NCHUNK    = 8;
constexpr int NSTAGE    = 3;
constexpr int A_U4      = 4 * 4 * 32;            // 512 uint4 (8 KB)
constexpr int B_U4      = 16 * 2 * 32;           // 1024 uint4 (16 KB)
constexpr int BUF_BYTES = (A_U4 + B_U4) * 16;    // 24576
constexpr int SMEM_BYTES = NSTAGE * BUF_BYTES;   // 73728

__device__ __forceinline__ void mma_f16(float d[4], uint32_t a0, uint32_t a1,
                                        uint32_t a2, uint32_t a3,
                                        uint32_t b0, uint32_t b1) {
    asm volatile(
        "mma.sync.aligned.m16n8k16.row.col.f32.f16.f16.f32 "
        "{%0,%1,%2,%3}, {%4,%5,%6,%7}, {%8,%9}, {%0,%1,%2,%3};"
        : "+f"(d[0]), "+f"(d[1]), "+f"(d[2]), "+f"(d[3])
        : "r"(a0), "r"(a1), "r"(a2), "r"(a3), "r"(b0), "r"(b1));
}

__global__ __launch_bounds__(512, 1) void pairre_mma_kernel(float* __restrict__ out) {
    extern __shared__ __align__(16) char smem[];
    const uint32_t sb = smem_u32(smem);

    const int tid  = threadIdx.x;
    const int wid  = tid >> 5;
    const int lane = tid & 31;
    const int ib  = blockIdx.y * 64;
    const int jb  = blockIdx.x * 128;
    const int ibA = blockIdx.y * 4;      // first mAtom
    const int jbA = blockIdx.x * 16;     // first nAtom

    const int wmA = wid >> 2;            // warp's mAtom (0..3)
    const int wnA = (wid & 3) * 4;       // warp's first nAtom (0..12)
    const int g   = lane >> 2;
    const int t   = lane & 3;

    float d[4][4];
    #pragma unroll
    for (int na = 0; na < 4; na++)
        #pragma unroll
        for (int q = 0; q < 4; q++)
            d[na][q] = 0.0f;

    auto issue_chunk = [&](int c, int stage) {
        const uint32_t bufA = sb + stage * BUF_BYTES;
        const uint32_t bufB = bufA + A_U4 * 16;
        // A: 512 uint4 (4 mAtoms x 4 kAtoms x 32 lanes) — 1 per thread
        {
            int m   = tid >> 7;               // mAtom in tile
            int off = tid & 127;              // uint4 within mAtom segment
            CP_ASYNC16(bufA + (m * 128 + off) * 16,
                       &g_Apk[(((ibA + m) * 32 + 4 * c) * 32) * 4 + off * 4]);
        }
        // B: 1024 uint4 (16 nAtoms x 2 kPairs x 32 lanes) — 2 per thread
        #pragma unroll
        for (int p = 0; p < 2; p++) {
            int f4i = tid + p * 512;          // 0..1023
            int nA  = f4i >> 6;
            int off = f4i & 63;
            CP_ASYNC16(bufB + (nA * 64 + off) * 16,
                       &g_Tpk[(((jbA + nA) * 16 + 2 * c) * 32) * 4 + off * 4]);
        }
        CP_COMMIT();
    };

    issue_chunk(0, 0);
    issue_chunk(1, 1);

    for (int c = 0; c < NCHUNK; c++) {
        if (c + 1 < NCHUNK) { CP_WAIT(1); } else { CP_WAIT(0); }
        __syncthreads();
        if (c + 2 < NCHUNK) issue_chunk(c + 2, (c + 2) % NSTAGE);

        const int stage = c % NSTAGE;
        const uint4* SA4 = reinterpret_cast<const uint4*>(smem + stage * BUF_BYTES);
        const uint4* SB4 = SA4 + A_U4;

        #pragma unroll
        for (int kp = 0; kp < 2; kp++) {
            uint4 a0v = SA4[(wmA * 4 + 2 * kp)     * 32 + lane];
            uint4 a1v = SA4[(wmA * 4 + 2 * kp + 1) * 32 + lane];
            #pragma unroll
            for (int na = 0; na < 4; na++) {
                uint4 bv = SB4[((wnA + na) * 2 + kp) * 32 + lane];
                mma_f16(d[na], a0v.x, a0v.y, a0v.z, a0v.w, bv.x, bv.y);
                mma_f16(d[na], a1v.x, a1v.y, a1v.z, a1v.w, bv.z, bv.w);
            }
        }
    }

    // Epilogue: out[i,j] = -sqrt(max(d + alpha_i, 0))
    const int i0 = ib + wmA * 16 + g;
    const float al0 = g_alpha[i0];
    const float al1 = g_alpha[i0 + 8];
    #pragma unroll
    for (int na = 0; na < 4; na++) {
        const int j = jb + (wnA + na) * 8 + t * 2;
        float2 v0, v1;
        v0.x = -sqrtf(fmaxf(d[na][0] + al0, 0.0f));
        v0.y = -sqrtf(fmaxf(d[na][1] + al0, 0.0f));
        v1.x = -sqrtf(fmaxf(d[na][2] + al1, 0.0f));
        v1.y = -sqrtf(fmaxf(d[na][3] + al1, 0.0f));
        *reinterpret_cast<float2*>(&out[i0 * NNEG + j])       = v0;
        *reinterpret_cast<float2*>(&out[(i0 + 8) * NNEG + j]) = v1;
    }
}

// ---------------------------------------------------------------------------
// Launch
// ---------------------------------------------------------------------------
extern "C" void kernel_launch(void* const* d_in, const int* in_sizes, int n_in,
                              void* d_out, int out_size) {
    const float* head = (const float*)d_in[0];   // (512, 256)
    const float* tail = (const float*)d_in[1];   // (1, 2048, 256)
    const float* rel  = (const float*)d_in[2];   // (1000, 512)
    const int*   rid  = (const int*)d_in[3];     // (512,) int32 on the wire
    float* out = (float*)d_out;                  // (512, 2048)

    cudaFuncSetAttribute(pairre_mma_kernel,
                         cudaFuncAttributeMaxDynamicSharedMemorySize, SMEM_BYTES);

    prep_kernel<<<32 + NNEG / 8, 256>>>(head, tail, rel, rid);   // 288 blocks

    dim3 grid(NNEG / 128, BATCH / 64);   // (16, 8) = 128 CTAs
    pairre_mma_kernel<<<grid, 512, SMEM_BYTES>>>(out);
}